// round 14
// baseline (speedup 1.0000x reference)
#include <cuda_runtime.h>
#include <cuda_fp16.h>
#include <math.h>
#include <stdint.h>

// Problem constants
#define NN   50000
#define TT   4
#define CC   128
#define FF   128
#define KK   3
#define EE   800000
#define MPAD 50048          // 391 * 128
#define NB   384            // fp16 basis row stride (3 blocks of 128)

#define SWZ(b) ((b) ^ (((b) >> 3) & 0x70))

// ---------------------------------------------------------------------------
// Device scratch
// ---------------------------------------------------------------------------
__device__ __align__(16) __half g_Bxf [(size_t)TT * MPAD * NB];   // x basis (Xp|Tx1x|Tx2x)
__device__ __align__(16) __half g_Bhf [(size_t)MPAD * NB];        // h basis (H|Tx1h|Tx2h)
__device__ __align__(16) __half g_Z   [(size_t)MPAD * 512];       // gate pre-activations fp16
__device__ __align__(16) float  g_Cst [(size_t)MPAD * 128];
__device__ __align__(16) __half g_WT  [512 * 768];                // W fp16, [n][k]
__device__ __align__(16) __half g_Wp  [128 * 128];                // Wpool fp16 [c][f]
__device__ __align__(16) float  g_bias[512];
__device__ int   g_es[EE];
__device__ int   g_ed[EE];
__device__ int   g_deg[NN];
__device__ int   g_cnt[NN];
__device__ float g_dinv[NN];
__device__ int   g_rowptr[NN + 1];
__device__ int   g_cursor[NN];
__device__ int   g_col[EE];
__device__ float g_val[EE];
__device__ int   g_flag64;

__device__ __forceinline__ uint32_t pack_h2(float a, float b) {
    __half2 h = __floats2half2_rn(a, b);
    return *(uint32_t*)&h;
}
__device__ __forceinline__ float4 h4f(uint2 u) {
    __half2 a = *(__half2*)&u.x, b = *(__half2*)&u.y;
    float2 f0 = __half22float2(a), f1 = __half22float2(b);
    return make_float4(f0.x, f0.y, f1.x, f1.y);
}
__device__ __forceinline__ uint32_t smem_u32(const void* p) {
    uint32_t a;
    asm("{ .reg .u64 t; cvta.to.shared.u64 t, %1; cvt.u32.u64 %0, t; }" : "=r"(a) : "l"(p));
    return a;
}
__device__ __forceinline__ float sigmoidf(float x) { return 1.f / (1.f + expf(-x)); }

// ---------------------------------------------------------------------------
// Launch 1 (stream 0): int64 detect + zero Cst/counters
// (Bhf needs NO zeroing: pad rows are never written and stay zero from module
//  load; rows < NN of block0 are written by gate(t=0) before any consumer.)
// ---------------------------------------------------------------------------
__global__ void k_init(const void* edges) {
    if (blockIdx.x == 0 && threadIdx.x == 0) {
        const long long* p = (const long long*)edges;
        int ok = 1;
        for (int i = 0; i < 512; ++i) {
            long long v = p[i];
            if (v < 0 || v >= NN) { ok = 0; break; }
        }
        g_flag64 = ok;
    }
    const long s0 = (long)MPAD * 32;      // Cst as float4
    const long s1 = 2 * (NN / 4);         // deg + cnt as int4
    const long total = s0 + s1;
    const float4 z4 = make_float4(0.f, 0.f, 0.f, 0.f);
    long i = (long)blockIdx.x * blockDim.x + threadIdx.x;
    long stride = (long)gridDim.x * blockDim.x;
    for (; i < total; i += stride) {
        if (i < s0) ((float4*)g_Cst)[i] = z4;
        else {
            long j = i - s0;
            if (j < NN / 4) ((int4*)g_deg)[j] = make_int4(0, 0, 0, 0);
            else            ((int4*)g_cnt)[j - NN / 4] = make_int4(0, 0, 0, 0);
        }
    }
}

// Launch 2 (stream 0): convert + degree counting
__global__ void k_convcount(const void* edges) {
    int i = blockIdx.x * blockDim.x + threadIdx.x;
    if (i >= 2 * EE) return;
    int v;
    if (g_flag64) v = (int)((const long long*)edges)[i];
    else          v = ((const int*)edges)[i];
    if (i < EE) { g_es[i] = v; atomicAdd(&g_deg[v], 1); }
    else        { g_ed[i - EE] = v; atomicAdd(&g_cnt[v], 1); }
}

// Launch 3 (stream 0): block 0 = exclusive scan; others = dinv
__global__ void k_scan_dinv() {
    if (blockIdx.x == 0) {
        __shared__ int sh[1024];
        const int t = threadIdx.x;
        const int CH = (NN + 1023) / 1024;
        int s = 0;
        int base0 = t * CH;
        for (int j = 0; j < CH; ++j) { int idx = base0 + j; if (idx < NN) s += g_cnt[idx]; }
        sh[t] = s;
        __syncthreads();
        for (int off = 1; off < 1024; off <<= 1) {
            int v = (t >= off) ? sh[t - off] : 0;
            __syncthreads();
            sh[t] += v;
            __syncthreads();
        }
        int run = (t == 0) ? 0 : sh[t - 1];
        for (int j = 0; j < CH; ++j) {
            int idx = base0 + j;
            if (idx < NN) { g_rowptr[idx] = run; g_cursor[idx] = run; run += g_cnt[idx]; }
        }
        if (t == 1023) g_rowptr[NN] = EE;
    } else {
        int i = (blockIdx.x - 1) * 1024 + threadIdx.x;
        if (i < NN) {
            int d = g_deg[i];
            g_dinv[i] = (d > 0) ? rsqrtf((float)d) : 0.0f;
        }
    }
}

// Launch 4 (stream 0): CSR fill
__global__ void k_fill() {
    int i = blockIdx.x * blockDim.x + threadIdx.x;
    if (i >= EE) return;
    int s = g_es[i], d = g_ed[i];
    int pos = atomicAdd(&g_cursor[d], 1);
    g_col[pos] = s;
    g_val[pos] = -(g_dinv[s] * g_dinv[d]);
}

// Launch (side stream): weight prep
__global__ void k_prep(const float* __restrict__ convW, const float* __restrict__ convb,
                       const float* __restrict__ gateb, const float* __restrict__ Wpool) {
    int i = blockIdx.x * blockDim.x + threadIdx.x;
    if (i < 512 * 768) {
        int cc = i / 768, r = i % 768;
        int kblk = r >> 7, rin = r & 127;
        int gate = cc >> 7, ch = cc & 127;
        int k   = kblk % 3;
        int idx = (kblk < 3) ? (2 * gate) : (2 * gate + 1);
        float v = convW[((size_t)(idx * KK + k)) * CC * CC + rin * CC + ch];
        g_WT[i] = __float2half_rn(v);
    }
    if (i < 512) {
        int gate = i / 128, c = i % 128;
        g_bias[i] = convb[(2 * gate) * CC + c] + convb[(2 * gate + 1) * CC + c] + gateb[gate * CC + c];
    }
    if (i < 128 * 128) {
        g_Wp[i] = __float2half_rn(Wpool[i]);
    }
}

// ---------------------------------------------------------------------------
// mma.sync fp16 GEMM, 3-stage cp.async, templated N tile (128 or 256).
// AF32: A source is fp32 [t*NN + n][128] (X input), converted inline; rows
//       mapped m = t*MPAD + n with n >= NN zero-filled.
// ---------------------------------------------------------------------------
__device__ __forceinline__ void ldsm4(uint32_t addr, uint32_t* r) {
    asm volatile("ldmatrix.sync.aligned.m8n8.x4.shared.b16 {%0,%1,%2,%3}, [%4];"
        : "=r"(r[0]), "=r"(r[1]), "=r"(r[2]), "=r"(r[3]) : "r"(addr));
}
__device__ __forceinline__ void mma16816(float* d, const uint32_t* a, const uint32_t* b) {
    asm volatile("mma.sync.aligned.m16n8k16.row.col.f32.f16.f16.f32 "
        "{%0,%1,%2,%3}, {%4,%5,%6,%7}, {%8,%9}, {%0,%1,%2,%3};"
        : "+f"(d[0]), "+f"(d[1]), "+f"(d[2]), "+f"(d[3])
        : "r"(a[0]), "r"(a[1]), "r"(a[2]), "r"(a[3]), "r"(b[0]), "r"(b[1]));
}
__device__ __forceinline__ void cp16(uint32_t dst, const void* src) {
    asm volatile("cp.async.cg.shared.global [%0], [%1], 16;" :: "r"(dst), "l"(src));
}

#define STAGES 3

template<int NCOLS, int MINCTA, bool AF32>
__global__ void __launch_bounds__(256, MINCTA) k_mgemm(
    const void* __restrict__ Ax, const void* __restrict__ Ah2,
    int kcx, int lda,
    const __half* __restrict__ B, int ldb,
    int K,
    __half* __restrict__ oF, int ldo)
{
    constexpr int NTL   = NCOLS / 32;
    constexpr int NPL   = NCOLS / 64;
    constexpr uint32_t GBUF = 16384u + (uint32_t)NCOLS * 128u;
    constexpr int LOADI = (1024 + NCOLS * 8) / 256;

    extern __shared__ char sm[];
    const int tid  = threadIdx.x;
    const int wid  = tid >> 5;
    const int lane = tid & 31;
    const int rowTile = blockIdx.y * 128;
    const int colTile = blockIdx.x * NCOLS;
    const int warp_m = (wid >> 2) * 64;
    const int warp_n = (wid & 3) * (NCOLS / 4);
    const uint32_t smb = smem_u32(sm);
    const int nch = K >> 6;

    float d[4][NTL][4];
#pragma unroll
    for (int a = 0; a < 4; ++a)
#pragma unroll
        for (int b2 = 0; b2 < NTL; ++b2)
#pragma unroll
            for (int q = 0; q < 4; ++q) d[a][b2][q] = 0.f;

    auto issue = [&](int c) {
        const uint32_t stOff = (uint32_t)(c % STAGES) * GBUF;
        const uint32_t dstBase = smb + stOff;
        const int ca = (c < kcx) ? c : c - kcx;
#pragma unroll
        for (int it = 0; it < LOADI; ++it) {
            int i = tid + it * 256;
            if (i < 1024) {
                int r = i >> 3, f = i & 7;
                uint32_t doff = SWZ((uint32_t)(r * 128 + f * 16));
                if (AF32) {
                    int gr = rowTile + r;
                    int tt = gr / MPAD;
                    int n  = gr - tt * MPAD;
                    uint4 q = make_uint4(0u, 0u, 0u, 0u);
                    if (n < NN) {
                        const float* sf = (const float*)Ax + ((size_t)tt * NN + n) * 128 + ca * 64 + f * 8;
                        float4 a0 = *(const float4*)sf;
                        float4 a1 = *(const float4*)(sf + 4);
                        q = make_uint4(pack_h2(a0.x, a0.y), pack_h2(a0.z, a0.w),
                                       pack_h2(a1.x, a1.y), pack_h2(a1.z, a1.w));
                    }
                    *(uint4*)(sm + stOff + doff) = q;
                } else {
                    const __half* ab = (const __half*)((c < kcx) ? Ax : Ah2);
                    const void* src = ab + (size_t)(rowTile + r) * lda + ca * 64 + f * 8;
                    cp16(dstBase + doff, src);
                }
            } else {
                int j = i - 1024;
                int r = j >> 3, f = j & 7;
                const void* src = B + (size_t)(colTile + r) * ldb + c * 64 + f * 8;
                cp16(dstBase + 16384u + SWZ((uint32_t)(r * 128 + f * 16)), src);
            }
        }
        asm volatile("cp.async.commit_group;" ::: "memory");
    };

    issue(0);
    if (nch > 1) issue(1);
    if (nch > 2) issue(2);

    for (int c = 0; c < nch; ++c) {
        int w = nch - 1 - c;
        if (w >= 2)      asm volatile("cp.async.wait_group 2;" ::: "memory");
        else if (w == 1) asm volatile("cp.async.wait_group 1;" ::: "memory");
        else             asm volatile("cp.async.wait_group 0;" ::: "memory");
        __syncthreads();

        const uint32_t sm0 = smb + (uint32_t)(c % STAGES) * GBUF;
        const int laneRowA = warp_m + (lane & 15);
        const uint32_t kbA = (uint32_t)((lane >> 4) * 16);
        const int nrowB = warp_n + (lane & 7) + ((lane >> 4) << 3);
        const uint32_t kbB = (uint32_t)(((lane >> 3) & 1) * 16);

#pragma unroll
        for (int ks = 0; ks < 4; ++ks) {
            uint32_t a[4][4], bb[NTL][2];
#pragma unroll
            for (int mt = 0; mt < 4; ++mt) {
                uint32_t off = SWZ((uint32_t)((laneRowA + mt * 16) * 128) + ks * 32 + kbA);
                ldsm4(sm0 + off, a[mt]);
            }
#pragma unroll
            for (int np = 0; np < NPL; ++np) {
                uint32_t off = SWZ((uint32_t)((nrowB + np * 16) * 128) + ks * 32 + kbB);
                uint32_t r0[4];
                ldsm4(sm0 + 16384u + off, r0);
                bb[2 * np][0] = r0[0]; bb[2 * np][1] = r0[1];
                bb[2 * np + 1][0] = r0[2]; bb[2 * np + 1][1] = r0[3];
            }
#pragma unroll
            for (int mt = 0; mt < 4; ++mt)
#pragma unroll
                for (int nt = 0; nt < NTL; ++nt)
                    mma16816(d[mt][nt], a[mt], bb[nt]);
        }
        if (c + STAGES < nch) {
            __syncthreads();
            issue(c + STAGES);
        }
    }

#pragma unroll
    for (int mt = 0; mt < 4; ++mt) {
        int m0 = rowTile + warp_m + mt * 16 + (lane >> 2);
#pragma unroll
        for (int nt = 0; nt < NTL; ++nt) {
            int n0 = colTile + warp_n + nt * 8 + (lane & 3) * 2;
#pragma unroll
            for (int half = 0; half < 2; ++half) {
                int m = m0 + half * 8;
                float v0 = d[mt][nt][half * 2], v1 = d[mt][nt][half * 2 + 1];
                *(uint32_t*)&oF[(size_t)m * ldo + n0] = pack_h2(v0, v1);
            }
        }
    }
}

// ---------------------------------------------------------------------------
// Chebyshev propagation on fp16 basis, 4-wide MLP edge loop, fp32 accumulate.
// ---------------------------------------------------------------------------
__global__ void k_prop1(const __half* __restrict__ in, __half* __restrict__ oh, int nWarp)
{
    int gw = (blockIdx.x * blockDim.x + threadIdx.x) >> 5;
    int lane = threadIdx.x & 31;
    if (gw >= nWarp) return;
    int t = gw / NN;
    int n = gw - t * NN;
    const __half* base = in + (size_t)t * MPAD * NB + lane * 4;

    int e = g_rowptr[n], end = g_rowptr[n + 1];
    float4 acc = make_float4(0.f, 0.f, 0.f, 0.f);
    for (; e + 4 <= end; e += 4) {
        int s0 = g_col[e], s1 = g_col[e + 1], s2 = g_col[e + 2], s3 = g_col[e + 3];
        float w0 = g_val[e], w1 = g_val[e + 1], w2 = g_val[e + 2], w3 = g_val[e + 3];
        uint2 u0 = *(const uint2*)(base + (size_t)s0 * NB);
        uint2 u1 = *(const uint2*)(base + (size_t)s1 * NB);
        uint2 u2 = *(const uint2*)(base + (size_t)s2 * NB);
        uint2 u3 = *(const uint2*)(base + (size_t)s3 * NB);
        float4 v0 = h4f(u0), v1 = h4f(u1), v2 = h4f(u2), v3 = h4f(u3);
        acc.x += w0 * v0.x + w1 * v1.x + w2 * v2.x + w3 * v3.x;
        acc.y += w0 * v0.y + w1 * v1.y + w2 * v2.y + w3 * v3.y;
        acc.z += w0 * v0.z + w1 * v1.z + w2 * v2.z + w3 * v3.z;
        acc.w += w0 * v0.w + w1 * v1.w + w2 * v2.w + w3 * v3.w;
    }
    for (; e < end; ++e) {
        float w = g_val[e];
        float4 v = h4f(*(const uint2*)(base + (size_t)g_col[e] * NB));
        acc.x += w * v.x; acc.y += w * v.y; acc.z += w * v.z; acc.w += w * v.w;
    }
    uint2 u;
    u.x = pack_h2(acc.x, acc.y);
    u.y = pack_h2(acc.z, acc.w);
    *(uint2*)(oh + (size_t)t * MPAD * NB + (size_t)n * NB + lane * 4) = u;
}

__global__ void k_prop2k(const __half* __restrict__ in, const __half* __restrict__ sub,
                         __half* __restrict__ oh, int nWarp)
{
    int gw = (blockIdx.x * blockDim.x + threadIdx.x) >> 5;
    int lane = threadIdx.x & 31;
    if (gw >= nWarp) return;
    int t = gw / NN;
    int n = gw - t * NN;
    size_t so = (size_t)t * MPAD * NB;
    const __half* base = in + so + lane * 4;

    int e = g_rowptr[n], end = g_rowptr[n + 1];
    float4 acc = make_float4(0.f, 0.f, 0.f, 0.f);
    for (; e + 4 <= end; e += 4) {
        int s0 = g_col[e], s1 = g_col[e + 1], s2 = g_col[e + 2], s3 = g_col[e + 3];
        float w0 = g_val[e], w1 = g_val[e + 1], w2 = g_val[e + 2], w3 = g_val[e + 3];
        uint2 u0 = *(const uint2*)(base + (size_t)s0 * NB);
        uint2 u1 = *(const uint2*)(base + (size_t)s1 * NB);
        uint2 u2 = *(const uint2*)(base + (size_t)s2 * NB);
        uint2 u3 = *(const uint2*)(base + (size_t)s3 * NB);
        float4 v0 = h4f(u0), v1 = h4f(u1), v2 = h4f(u2), v3 = h4f(u3);
        acc.x += w0 * v0.x + w1 * v1.x + w2 * v2.x + w3 * v3.x;
        acc.y += w0 * v0.y + w1 * v1.y + w2 * v2.y + w3 * v3.y;
        acc.z += w0 * v0.z + w1 * v1.z + w2 * v2.z + w3 * v3.z;
        acc.w += w0 * v0.w + w1 * v1.w + w2 * v2.w + w3 * v3.w;
    }
    for (; e < end; ++e) {
        float w = g_val[e];
        float4 v = h4f(*(const uint2*)(base + (size_t)g_col[e] * NB));
        acc.x += w * v.x; acc.y += w * v.y; acc.z += w * v.z; acc.w += w * v.w;
    }
    float4 sv = h4f(*(const uint2*)(sub + so + (size_t)n * NB + lane * 4));
    uint2 u;
    u.x = pack_h2(2.f * acc.x - sv.x, 2.f * acc.y - sv.y);
    u.y = pack_h2(2.f * acc.z - sv.z, 2.f * acc.w - sv.w);
    *(uint2*)(oh + so + (size_t)n * NB + lane * 4) = u;
}

// ---------------------------------------------------------------------------
// Gate fusion (half2, 2 channels/thread)
// ---------------------------------------------------------------------------
__global__ void k_gate(const float* __restrict__ pw, float* __restrict__ out, int t) {
    int i = blockIdx.x * blockDim.x + threadIdx.x;
    if (i >= NN * 64) return;
    int n = i >> 6, c = (i & 63) * 2;

    const __half* z = &g_Z[(size_t)n * 512];
    float2 zi = __half22float2(*(const __half2*)&z[c]);
    float2 zf = __half22float2(*(const __half2*)&z[128 + c]);
    float2 zc = __half22float2(*(const __half2*)&z[256 + c]);
    float2 zo = __half22float2(*(const __half2*)&z[384 + c]);
    float2 cold = *(const float2*)&g_Cst[(size_t)n * 128 + c];

    float2 h2, cn2;
#pragma unroll
    for (int q = 0; q < 2; ++q) {
        int cc = c + q;
        float zzi = q ? zi.y : zi.x, zzf = q ? zf.y : zf.x;
        float zzc = q ? zc.y : zc.x, zzo = q ? zo.y : zo.x;
        float co = q ? cold.y : cold.x;
        float I  = sigmoidf(zzi + g_bias[cc]       + pw[cc]       * co);
        float F  = sigmoidf(zzf + g_bias[128 + cc] + pw[128 + cc] * co);
        float Tc = tanhf  (zzc + g_bias[256 + cc]);
        float cnew = F * co + I * Tc;
        float O  = sigmoidf(zzo + g_bias[384 + cc] + pw[256 + cc] * cnew);
        float h  = O * tanhf(cnew);
        if (q) { h2.y = h; cn2.y = cnew; } else { h2.x = h; cn2.x = cnew; }
    }

    *(float2*)&g_Cst[(size_t)n * 128 + c] = cn2;
    *(__half2*)&g_Bhf[(size_t)n * NB + c] = __floats2half2_rn(h2.x, h2.y);
    *(float2*)&out[((size_t)n * TT + t) * CC + c] = h2;
}

// ---------------------------------------------------------------------------
// Host launcher — fork/join: edge chain (stream 0) || weights+pool (side stream)
// ---------------------------------------------------------------------------
extern "C" void kernel_launch(void* const* d_in, const int* in_sizes, int n_in,
                              void* d_out, int out_size)
{
    const float* X     = (const float*)d_in[0];
    const void*  edges = d_in[1];
    const float* Wpool = (const float*)d_in[2];
    const float* convW = (const float*)d_in[3];
    const float* convb = (const float*)d_in[4];
    const float* pw    = (const float*)d_in[5];
    const float* gb    = (const float*)d_in[6];
    float* out = (float*)d_out;

    __half *Z, *Bxf, *Bhf, *WT, *Wp;
    cudaGetSymbolAddress((void**)&Z,   g_Z);
    cudaGetSymbolAddress((void**)&Bxf, g_Bxf);
    cudaGetSymbolAddress((void**)&Bhf, g_Bhf);
    cudaGetSymbolAddress((void**)&WT,  g_WT);
    cudaGetSymbolAddress((void**)&Wp,  g_Wp);

    const uint32_t SM128 = STAGES * (16384u + 128u * 128u);   // 96 KB
    const uint32_t SM256 = STAGES * (16384u + 256u * 128u);   // 144 KB
    cudaFuncSetAttribute((const void*)k_mgemm<128, 2, true>,  cudaFuncAttributeMaxDynamicSharedMemorySize, SM128);
    cudaFuncSetAttribute((const void*)k_mgemm<256, 1, false>, cudaFuncAttributeMaxDynamicSharedMemorySize, SM256);

    const size_t SLF = (size_t)MPAD * NB;    // fp16 t-slice stride

    // Side stream + fork/join events. Created per call, intentionally never
    // destroyed: kernel_launch runs only a handful of times, and the captured
    // graph needs the handles valid across replays. Destroying a stream that
    // participated in capture before EndCapture is a hazard; leaking two
    // handles is not.
    cudaStream_t s2;
    cudaStreamCreate(&s2);
    cudaEvent_t evF, evJ;
    cudaEventCreateWithFlags(&evF, cudaEventDisableTiming);
    cudaEventCreateWithFlags(&evJ, cudaEventDisableTiming);

    // fork
    cudaEventRecord(evF, 0);
    cudaStreamWaitEvent(s2, evF, 0);

    // stream 0: edge/CSR chain
    k_init<<<2048, 256>>>(edges);
    k_convcount<<<(2 * EE + 255) / 256, 256>>>(edges);
    k_scan_dinv<<<50, 1024>>>();
    k_fill<<<(EE + 255) / 256, 256>>>();

    // side stream: weight prep + pool GEMM (all timesteps, fp32 X inline)
    k_prep<<<(512 * 768 + 255) / 256, 256, 0, s2>>>(convW, convb, gb, Wpool);
    k_mgemm<128, 2, true><<<dim3(1, TT * MPAD / 128), 256, SM128, s2>>>(
        X, X, 99, 128, Wp, 128, 128, Bxf, NB);

    // join
    cudaEventRecord(evJ, s2);
    cudaStreamWaitEvent(0, evJ, 0);

    // x-path Chebyshev basis, all timesteps batched
    k_prop1<<<TT * NN / 4, 128>>>(Bxf, Bxf + 128, TT * NN);
    k_prop2k<<<TT * NN / 4, 128>>>(Bxf + 128, Bxf, Bxf + 256, TT * NN);

    // recurrent loop
    for (int t = 0; t < TT; ++t) {
        if (t > 0) {
            k_prop1<<<NN / 4, 128>>>(Bhf, Bhf + 128, NN);
            k_prop2k<<<NN / 4, 128>>>(Bhf + 128, Bhf, Bhf + 256, NN);
        }
        int Kt = (t == 0) ? 384 : 768;
        k_mgemm<256, 1, false><<<dim3(2, MPAD / 128), 256, SM256>>>(
            Bxf + (size_t)t * SLF, Bhf, 6, NB,
            WT, 768, Kt, Z, 512);
        k_gate<<<(NN * 64 + 255) / 256, 256>>>(pw, out, t);
    }
}

// round 15
// speedup vs baseline: 1.0573x; 1.0573x over previous
#include <cuda_runtime.h>
#include <cuda_fp16.h>
#include <math.h>
#include <stdint.h>

// Problem constants
#define NN   50000
#define TT   4
#define CC   128
#define FF   128
#define KK   3
#define EE   800000
#define MPAD 50048          // 391 * 128
#define NB   384            // fp16 basis row stride (3 blocks of 128)

#define SWZ(b) ((b) ^ (((b) >> 3) & 0x70))

// ---------------------------------------------------------------------------
// Device scratch
// ---------------------------------------------------------------------------
__device__ __align__(16) __half g_Bxf [(size_t)TT * MPAD * NB];   // x basis (Xp|Tx1x|Tx2x)
__device__ __align__(16) __half g_Bhf [(size_t)MPAD * NB];        // h basis (H|Tx1h|Tx2h); pads stay 0
__device__ __align__(16) __half g_Z   [(size_t)MPAD * 512];       // gate pre-activations fp16
__device__ __align__(16) float  g_Cst [(size_t)MPAD * 128];
__device__ __align__(16) __half g_WT  [512 * 768];                // W fp16, [n][k]
__device__ __align__(16) __half g_Wp  [128 * 128];                // Wpool fp16 [c][f]
__device__ __align__(16) float  g_bias[512];
__device__ int   g_es[EE];
__device__ int   g_ed[EE];
__device__ int   g_deg[NN];   // zero at entry of every call (self-restoring)
__device__ int   g_cnt[NN];   // zero at entry of every call (self-restoring)
__device__ float g_dinv[NN];
__device__ int   g_rowptr[NN + 1];
__device__ int   g_cursor[NN];
__device__ int   g_col[EE];
__device__ float g_val[EE];
__device__ int   g_flag64;

__device__ __forceinline__ uint32_t pack_h2(float a, float b) {
    __half2 h = __floats2half2_rn(a, b);
    return *(uint32_t*)&h;
}
__device__ __forceinline__ float4 h4f(uint2 u) {
    __half2 a = *(__half2*)&u.x, b = *(__half2*)&u.y;
    float2 f0 = __half22float2(a), f1 = __half22float2(b);
    return make_float4(f0.x, f0.y, f1.x, f1.y);
}
__device__ __forceinline__ uint32_t smem_u32(const void* p) {
    uint32_t a;
    asm("{ .reg .u64 t; cvta.to.shared.u64 t, %1; cvt.u32.u64 %0, t; }" : "=r"(a) : "l"(p));
    return a;
}
// MUFU-path transcendentals (independent of -use_fast_math)
__device__ __forceinline__ float fsigmoid(float x) {
    return __fdividef(1.f, 1.f + __expf(-x));
}
__device__ __forceinline__ float ftanh(float x) {
    return 1.f - __fdividef(2.f, __expf(2.f * x) + 1.f);
}

// ---------------------------------------------------------------------------
// Launch 1: int64 detect + zero Cst (counters are self-restoring; Bhf pads
// stay zero from module load and block0 is written by gate(t=0) first)
// ---------------------------------------------------------------------------
__global__ void k_init(const void* edges) {
    if (blockIdx.x == 0 && threadIdx.x == 0) {
        const long long* p = (const long long*)edges;
        int ok = 1;
        for (int i = 0; i < 512; ++i) {
            long long v = p[i];
            if (v < 0 || v >= NN) { ok = 0; break; }
        }
        g_flag64 = ok;
    }
    const long total = (long)MPAD * 32;   // Cst as float4
    const float4 z4 = make_float4(0.f, 0.f, 0.f, 0.f);
    long i = (long)blockIdx.x * blockDim.x + threadIdx.x;
    long stride = (long)gridDim.x * blockDim.x;
    for (; i < total; i += stride) ((float4*)g_Cst)[i] = z4;
}

// Launch 2: convert + degree counting
__global__ void k_convcount(const void* edges) {
    int i = blockIdx.x * blockDim.x + threadIdx.x;
    if (i >= 2 * EE) return;
    int v;
    if (g_flag64) v = (int)((const long long*)edges)[i];
    else          v = ((const int*)edges)[i];
    if (i < EE) { g_es[i] = v; atomicAdd(&g_deg[v], 1); }
    else        { g_ed[i - EE] = v; atomicAdd(&g_cnt[v], 1); }
}

// Launch 3: block 0 = exclusive scan of cnt (zeroing cnt after read);
// other blocks = dinv from deg (zeroing deg after read).
__global__ void k_scan_dinv() {
    if (blockIdx.x == 0) {
        __shared__ int sh[1024];
        const int t = threadIdx.x;
        const int CH = (NN + 1023) / 1024;
        int loc[49];
        int s = 0;
        int base0 = t * CH;
        for (int j = 0; j < CH; ++j) {
            int idx = base0 + j;
            int c = 0;
            if (idx < NN) { c = g_cnt[idx]; g_cnt[idx] = 0; }
            loc[j] = c;
            s += c;
        }
        sh[t] = s;
        __syncthreads();
        for (int off = 1; off < 1024; off <<= 1) {
            int v = (t >= off) ? sh[t - off] : 0;
            __syncthreads();
            sh[t] += v;
            __syncthreads();
        }
        int run = (t == 0) ? 0 : sh[t - 1];
        for (int j = 0; j < CH; ++j) {
            int idx = base0 + j;
            if (idx < NN) { g_rowptr[idx] = run; g_cursor[idx] = run; run += loc[j]; }
        }
        if (t == 1023) g_rowptr[NN] = EE;
    } else {
        int i = (blockIdx.x - 1) * 1024 + threadIdx.x;
        if (i < NN) {
            int d = g_deg[i];
            g_deg[i] = 0;
            g_dinv[i] = (d > 0) ? rsqrtf((float)d) : 0.0f;
        }
    }
}

// Launch 4: CSR fill + weight prep (fused, block ranges)
#define FPS_FILL_BLK   3125
#define FPS_PREP_BLK   1536
__global__ void k_fps(const float* __restrict__ convW, const float* __restrict__ convb,
                      const float* __restrict__ gateb, const float* __restrict__ Wpool) {
    int b = blockIdx.x;
    if (b < FPS_FILL_BLK) {
        int i = b * 256 + threadIdx.x;
        if (i >= EE) return;
        int s = g_es[i], d = g_ed[i];
        int pos = atomicAdd(&g_cursor[d], 1);
        g_col[pos] = s;
        g_val[pos] = -(g_dinv[s] * g_dinv[d]);
    } else {
        int i = (b - FPS_FILL_BLK) * 256 + threadIdx.x;
        if (i < 512 * 768) {
            int cc = i / 768, r = i % 768;
            int kblk = r >> 7, rin = r & 127;
            int gate = cc >> 7, ch = cc & 127;
            int k   = kblk % 3;
            int idx = (kblk < 3) ? (2 * gate) : (2 * gate + 1);
            float v = convW[((size_t)(idx * KK + k)) * CC * CC + rin * CC + ch];
            g_WT[i] = __float2half_rn(v);
        }
        if (i < 512) {
            int gate = i / 128, c = i % 128;
            g_bias[i] = convb[(2 * gate) * CC + c] + convb[(2 * gate + 1) * CC + c] + gateb[gate * CC + c];
        }
        if (i < 128 * 128) {
            g_Wp[i] = __float2half_rn(Wpool[i]);
        }
    }
}

// ---------------------------------------------------------------------------
// mma.sync fp16 GEMM, 3-stage cp.async, templated N tile (128 or 256).
// AF32: A source is fp32 [t*NN + n][128] (X input), converted inline; rows
//       mapped m = t*MPAD + n with n >= NN zero-filled.
// ---------------------------------------------------------------------------
__device__ __forceinline__ void ldsm4(uint32_t addr, uint32_t* r) {
    asm volatile("ldmatrix.sync.aligned.m8n8.x4.shared.b16 {%0,%1,%2,%3}, [%4];"
        : "=r"(r[0]), "=r"(r[1]), "=r"(r[2]), "=r"(r[3]) : "r"(addr));
}
__device__ __forceinline__ void mma16816(float* d, const uint32_t* a, const uint32_t* b) {
    asm volatile("mma.sync.aligned.m16n8k16.row.col.f32.f16.f16.f32 "
        "{%0,%1,%2,%3}, {%4,%5,%6,%7}, {%8,%9}, {%0,%1,%2,%3};"
        : "+f"(d[0]), "+f"(d[1]), "+f"(d[2]), "+f"(d[3])
        : "r"(a[0]), "r"(a[1]), "r"(a[2]), "r"(a[3]), "r"(b[0]), "r"(b[1]));
}
__device__ __forceinline__ void cp16(uint32_t dst, const void* src) {
    asm volatile("cp.async.cg.shared.global [%0], [%1], 16;" :: "r"(dst), "l"(src));
}

#define STAGES 3

template<int NCOLS, int MINCTA, bool AF32>
__global__ void __launch_bounds__(256, MINCTA) k_mgemm(
    const void* __restrict__ Ax, const void* __restrict__ Ah2,
    int kcx, int lda,
    const __half* __restrict__ B, int ldb,
    int K,
    __half* __restrict__ oF, int ldo)
{
    constexpr int NTL   = NCOLS / 32;
    constexpr int NPL   = NCOLS / 64;
    constexpr uint32_t GBUF = 16384u + (uint32_t)NCOLS * 128u;
    constexpr int LOADI = (1024 + NCOLS * 8) / 256;

    extern __shared__ char sm[];
    const int tid  = threadIdx.x;
    const int wid  = tid >> 5;
    const int lane = tid & 31;
    const int rowTile = blockIdx.y * 128;
    const int colTile = blockIdx.x * NCOLS;
    const int warp_m = (wid >> 2) * 64;
    const int warp_n = (wid & 3) * (NCOLS / 4);
    const uint32_t smb = smem_u32(sm);
    const int nch = K >> 6;

    float d[4][NTL][4];
#pragma unroll
    for (int a = 0; a < 4; ++a)
#pragma unroll
        for (int b2 = 0; b2 < NTL; ++b2)
#pragma unroll
            for (int q = 0; q < 4; ++q) d[a][b2][q] = 0.f;

    auto issue = [&](int c) {
        const uint32_t stOff = (uint32_t)(c % STAGES) * GBUF;
        const uint32_t dstBase = smb + stOff;
        const int ca = (c < kcx) ? c : c - kcx;
#pragma unroll
        for (int it = 0; it < LOADI; ++it) {
            int i = tid + it * 256;
            if (i < 1024) {
                int r = i >> 3, f = i & 7;
                uint32_t doff = SWZ((uint32_t)(r * 128 + f * 16));
                if (AF32) {
                    int gr = rowTile + r;
                    int tt = gr / MPAD;
                    int n  = gr - tt * MPAD;
                    uint4 q = make_uint4(0u, 0u, 0u, 0u);
                    if (n < NN) {
                        const float* sf = (const float*)Ax + ((size_t)tt * NN + n) * 128 + ca * 64 + f * 8;
                        float4 a0 = *(const float4*)sf;
                        float4 a1 = *(const float4*)(sf + 4);
                        q = make_uint4(pack_h2(a0.x, a0.y), pack_h2(a0.z, a0.w),
                                       pack_h2(a1.x, a1.y), pack_h2(a1.z, a1.w));
                    }
                    *(uint4*)(sm + stOff + doff) = q;
                } else {
                    const __half* ab = (const __half*)((c < kcx) ? Ax : Ah2);
                    const void* src = ab + (size_t)(rowTile + r) * lda + ca * 64 + f * 8;
                    cp16(dstBase + doff, src);
                }
            } else {
                int j = i - 1024;
                int r = j >> 3, f = j & 7;
                const void* src = B + (size_t)(colTile + r) * ldb + c * 64 + f * 8;
                cp16(dstBase + 16384u + SWZ((uint32_t)(r * 128 + f * 16)), src);
            }
        }
        asm volatile("cp.async.commit_group;" ::: "memory");
    };

    issue(0);
    if (nch > 1) issue(1);
    if (nch > 2) issue(2);

    for (int c = 0; c < nch; ++c) {
        int w = nch - 1 - c;
        if (w >= 2)      asm volatile("cp.async.wait_group 2;" ::: "memory");
        else if (w == 1) asm volatile("cp.async.wait_group 1;" ::: "memory");
        else             asm volatile("cp.async.wait_group 0;" ::: "memory");
        __syncthreads();

        const uint32_t sm0 = smb + (uint32_t)(c % STAGES) * GBUF;
        const int laneRowA = warp_m + (lane & 15);
        const uint32_t kbA = (uint32_t)((lane >> 4) * 16);
        const int nrowB = warp_n + (lane & 7) + ((lane >> 4) << 3);
        const uint32_t kbB = (uint32_t)(((lane >> 3) & 1) * 16);

#pragma unroll
        for (int ks = 0; ks < 4; ++ks) {
            uint32_t a[4][4], bb[NTL][2];
#pragma unroll
            for (int mt = 0; mt < 4; ++mt) {
                uint32_t off = SWZ((uint32_t)((laneRowA + mt * 16) * 128) + ks * 32 + kbA);
                ldsm4(sm0 + off, a[mt]);
            }
#pragma unroll
            for (int np = 0; np < NPL; ++np) {
                uint32_t off = SWZ((uint32_t)((nrowB + np * 16) * 128) + ks * 32 + kbB);
                uint32_t r0[4];
                ldsm4(sm0 + 16384u + off, r0);
                bb[2 * np][0] = r0[0]; bb[2 * np][1] = r0[1];
                bb[2 * np + 1][0] = r0[2]; bb[2 * np + 1][1] = r0[3];
            }
#pragma unroll
            for (int mt = 0; mt < 4; ++mt)
#pragma unroll
                for (int nt = 0; nt < NTL; ++nt)
                    mma16816(d[mt][nt], a[mt], bb[nt]);
        }
        if (c + STAGES < nch) {
            __syncthreads();
            issue(c + STAGES);
        }
    }

#pragma unroll
    for (int mt = 0; mt < 4; ++mt) {
        int m0 = rowTile + warp_m + mt * 16 + (lane >> 2);
#pragma unroll
        for (int nt = 0; nt < NTL; ++nt) {
            int n0 = colTile + warp_n + nt * 8 + (lane & 3) * 2;
#pragma unroll
            for (int half = 0; half < 2; ++half) {
                int m = m0 + half * 8;
                float v0 = d[mt][nt][half * 2], v1 = d[mt][nt][half * 2 + 1];
                *(uint32_t*)&oF[(size_t)m * ldo + n0] = pack_h2(v0, v1);
            }
        }
    }
}

// ---------------------------------------------------------------------------
// Chebyshev propagation on fp16 basis, 4-wide MLP edge loop, fp32 accumulate.
// ---------------------------------------------------------------------------
__global__ void k_prop1(const __half* __restrict__ in, __half* __restrict__ oh, int nWarp)
{
    int gw = (blockIdx.x * blockDim.x + threadIdx.x) >> 5;
    int lane = threadIdx.x & 31;
    if (gw >= nWarp) return;
    int t = gw / NN;
    int n = gw - t * NN;
    const __half* base = in + (size_t)t * MPAD * NB + lane * 4;

    int e = g_rowptr[n], end = g_rowptr[n + 1];
    float4 acc = make_float4(0.f, 0.f, 0.f, 0.f);
    for (; e + 4 <= end; e += 4) {
        int s0 = g_col[e], s1 = g_col[e + 1], s2 = g_col[e + 2], s3 = g_col[e + 3];
        float w0 = g_val[e], w1 = g_val[e + 1], w2 = g_val[e + 2], w3 = g_val[e + 3];
        uint2 u0 = *(const uint2*)(base + (size_t)s0 * NB);
        uint2 u1 = *(const uint2*)(base + (size_t)s1 * NB);
        uint2 u2 = *(const uint2*)(base + (size_t)s2 * NB);
        uint2 u3 = *(const uint2*)(base + (size_t)s3 * NB);
        float4 v0 = h4f(u0), v1 = h4f(u1), v2 = h4f(u2), v3 = h4f(u3);
        acc.x += w0 * v0.x + w1 * v1.x + w2 * v2.x + w3 * v3.x;
        acc.y += w0 * v0.y + w1 * v1.y + w2 * v2.y + w3 * v3.y;
        acc.z += w0 * v0.z + w1 * v1.z + w2 * v2.z + w3 * v3.z;
        acc.w += w0 * v0.w + w1 * v1.w + w2 * v2.w + w3 * v3.w;
    }
    for (; e < end; ++e) {
        float w = g_val[e];
        float4 v = h4f(*(const uint2*)(base + (size_t)g_col[e] * NB));
        acc.x += w * v.x; acc.y += w * v.y; acc.z += w * v.z; acc.w += w * v.w;
    }
    uint2 u;
    u.x = pack_h2(acc.x, acc.y);
    u.y = pack_h2(acc.z, acc.w);
    *(uint2*)(oh + (size_t)t * MPAD * NB + (size_t)n * NB + lane * 4) = u;
}

__global__ void k_prop2k(const __half* __restrict__ in, const __half* __restrict__ sub,
                         __half* __restrict__ oh, int nWarp)
{
    int gw = (blockIdx.x * blockDim.x + threadIdx.x) >> 5;
    int lane = threadIdx.x & 31;
    if (gw >= nWarp) return;
    int t = gw / NN;
    int n = gw - t * NN;
    size_t so = (size_t)t * MPAD * NB;
    const __half* base = in + so + lane * 4;

    int e = g_rowptr[n], end = g_rowptr[n + 1];
    float4 acc = make_float4(0.f, 0.f, 0.f, 0.f);
    for (; e + 4 <= end; e += 4) {
        int s0 = g_col[e], s1 = g_col[e + 1], s2 = g_col[e + 2], s3 = g_col[e + 3];
        float w0 = g_val[e], w1 = g_val[e + 1], w2 = g_val[e + 2], w3 = g_val[e + 3];
        uint2 u0 = *(const uint2*)(base + (size_t)s0 * NB);
        uint2 u1 = *(const uint2*)(base + (size_t)s1 * NB);
        uint2 u2 = *(const uint2*)(base + (size_t)s2 * NB);
        uint2 u3 = *(const uint2*)(base + (size_t)s3 * NB);
        float4 v0 = h4f(u0), v1 = h4f(u1), v2 = h4f(u2), v3 = h4f(u3);
        acc.x += w0 * v0.x + w1 * v1.x + w2 * v2.x + w3 * v3.x;
        acc.y += w0 * v0.y + w1 * v1.y + w2 * v2.y + w3 * v3.y;
        acc.z += w0 * v0.z + w1 * v1.z + w2 * v2.z + w3 * v3.z;
        acc.w += w0 * v0.w + w1 * v1.w + w2 * v2.w + w3 * v3.w;
    }
    for (; e < end; ++e) {
        float w = g_val[e];
        float4 v = h4f(*(const uint2*)(base + (size_t)g_col[e] * NB));
        acc.x += w * v.x; acc.y += w * v.y; acc.z += w * v.z; acc.w += w * v.w;
    }
    float4 sv = h4f(*(const uint2*)(sub + so + (size_t)n * NB + lane * 4));
    uint2 u;
    u.x = pack_h2(2.f * acc.x - sv.x, 2.f * acc.y - sv.y);
    u.y = pack_h2(2.f * acc.z - sv.z, 2.f * acc.w - sv.w);
    *(uint2*)(oh + so + (size_t)n * NB + lane * 4) = u;
}

// ---------------------------------------------------------------------------
// Gate fusion (half2, 2 channels/thread), MUFU fast-path transcendentals
// ---------------------------------------------------------------------------
__global__ void k_gate(const float* __restrict__ pw, float* __restrict__ out, int t) {
    int i = blockIdx.x * blockDim.x + threadIdx.x;
    if (i >= NN * 64) return;
    int n = i >> 6, c = (i & 63) * 2;

    const __half* z = &g_Z[(size_t)n * 512];
    float2 zi = __half22float2(*(const __half2*)&z[c]);
    float2 zf = __half22float2(*(const __half2*)&z[128 + c]);
    float2 zc = __half22float2(*(const __half2*)&z[256 + c]);
    float2 zo = __half22float2(*(const __half2*)&z[384 + c]);
    float2 cold = *(const float2*)&g_Cst[(size_t)n * 128 + c];

    float2 h2, cn2;
#pragma unroll
    for (int q = 0; q < 2; ++q) {
        int cc = c + q;
        float zzi = q ? zi.y : zi.x, zzf = q ? zf.y : zf.x;
        float zzc = q ? zc.y : zc.x, zzo = q ? zo.y : zo.x;
        float co = q ? cold.y : cold.x;
        float I  = fsigmoid(zzi + g_bias[cc]       + pw[cc]       * co);
        float F  = fsigmoid(zzf + g_bias[128 + cc] + pw[128 + cc] * co);
        float Tc = ftanh   (zzc + g_bias[256 + cc]);
        float cnew = F * co + I * Tc;
        float O  = fsigmoid(zzo + g_bias[384 + cc] + pw[256 + cc] * cnew);
        float h  = O * ftanh(cnew);
        if (q) { h2.y = h; cn2.y = cnew; } else { h2.x = h; cn2.x = cnew; }
    }

    *(float2*)&g_Cst[(size_t)n * 128 + c] = cn2;
    *(__half2*)&g_Bhf[(size_t)n * NB + c] = __floats2half2_rn(h2.x, h2.y);
    *(float2*)&out[((size_t)n * TT + t) * CC + c] = h2;
}

// ---------------------------------------------------------------------------
// Host launcher (serial, single stream)
// ---------------------------------------------------------------------------
extern "C" void kernel_launch(void* const* d_in, const int* in_sizes, int n_in,
                              void* d_out, int out_size)
{
    const float* X     = (const float*)d_in[0];
    const void*  edges = d_in[1];
    const float* Wpool = (const float*)d_in[2];
    const float* convW = (const float*)d_in[3];
    const float* convb = (const float*)d_in[4];
    const float* pw    = (const float*)d_in[5];
    const float* gb    = (const float*)d_in[6];
    float* out = (float*)d_out;

    __half *Z, *Bxf, *Bhf, *WT, *Wp;
    cudaGetSymbolAddress((void**)&Z,   g_Z);
    cudaGetSymbolAddress((void**)&Bxf, g_Bxf);
    cudaGetSymbolAddress((void**)&Bhf, g_Bhf);
    cudaGetSymbolAddress((void**)&WT,  g_WT);
    cudaGetSymbolAddress((void**)&Wp,  g_Wp);

    const uint32_t SM128 = STAGES * (16384u + 128u * 128u);   // 96 KB
    const uint32_t SM256 = STAGES * (16384u + 256u * 128u);   // 144 KB
    cudaFuncSetAttribute((const void*)k_mgemm<128, 2, true>,  cudaFuncAttributeMaxDynamicSharedMemorySize, SM128);
    cudaFuncSetAttribute((const void*)k_mgemm<256, 1, false>, cudaFuncAttributeMaxDynamicSharedMemorySize, SM256);

    const size_t SLF = (size_t)MPAD * NB;    // fp16 t-slice stride

    // 1-4: preprocessing
    k_init<<<2048, 256>>>(edges);
    k_convcount<<<(2 * EE + 255) / 256, 256>>>(edges);
    k_scan_dinv<<<50, 1024>>>();
    k_fps<<<FPS_FILL_BLK + FPS_PREP_BLK, 256>>>(convW, convb, gb, Wpool);

    // 5: pool GEMM, all timesteps, fp32 X converted inline: Xp -> Bxf block 0
    k_mgemm<128, 2, true><<<dim3(1, TT * MPAD / 128), 256, SM128>>>(
        X, X, 99, 128, Wp, 128, 128, Bxf, NB);

    // 6-7: x-path Chebyshev basis, all timesteps batched
    k_prop1<<<TT * NN / 4, 128>>>(Bxf, Bxf + 128, TT * NN);
    k_prop2k<<<TT * NN / 4, 128>>>(Bxf + 128, Bxf, Bxf + 256, TT * NN);

    // recurrent loop
    for (int t = 0; t < TT; ++t) {
        if (t > 0) {
            k_prop1<<<NN / 4, 128>>>(Bhf, Bhf + 128, NN);
            k_prop2k<<<NN / 4, 128>>>(Bhf + 128, Bhf, Bhf + 256, NN);
        }
        int Kt = (t == 0) ? 384 : 768;
        k_mgemm<256, 1, false><<<dim3(2, MPAD / 128), 256, SM256>>>(
            Bxf + (size_t)t * SLF, Bhf, 6, NB,
            WT, 768, Kt, Z, 512);
        k_gate<<<(NN * 64 + 255) / 256, 256>>>(pw, out, t);
    }
}